// round 1
// baseline (speedup 1.0000x reference)
#include <cuda_runtime.h>
#include <cuda_bf16.h>
#include <math.h>

#define BATCH   16
#define CIN     256
#define HH      56
#define WW      56
#define HEADS   4
#define CPER    64          // C_OUT / HEADS
#define HB_N    (HEADS*BATCH)   // 64
#define NPIX    (HH*WW)         // 3136
#define NOUT    (BATCH*HEADS*CPER*NPIX)  // 12,845,056
#define BN_EPS  1e-5f

// ---------------- device scratch (no allocations allowed) ----------------
__device__ float g_xavg[BATCH*CIN];
__device__ int   g_act_idx[HB_N*256];
__device__ float g_act_val[HB_N*256];
__device__ int   g_act_cnt[HB_N];
__device__ float g_lasso_part[HB_N];

// =====================================================================
// Kernel 1: BN(inference)+ReLU fused global average pool (xn not stored)
// grid = B*C blocks, 256 threads
// =====================================================================
__global__ void bn_pool_kernel(const float* __restrict__ x,
                               const float* __restrict__ gmm,
                               const float* __restrict__ bet,
                               const float* __restrict__ mea,
                               const float* __restrict__ var)
{
    int bc = blockIdx.x;            // b*CIN + c
    int c  = bc & (CIN-1);
    float a  = gmm[c] * rsqrtf(var[c] + BN_EPS);
    float sh = bet[c] - mea[c] * a;
    const float* xp = x + (size_t)bc * NPIX;
    float s = 0.f;
    for (int i = threadIdx.x; i < NPIX; i += 256)
        s += fmaxf(fmaf(xp[i], a, sh), 0.f);
    __shared__ float red[256];
    red[threadIdx.x] = s;
    __syncthreads();
    for (int st = 128; st > 0; st >>= 1) {
        if (threadIdx.x < st) red[threadIdx.x] += red[threadIdx.x + st];
        __syncthreads();
    }
    if (threadIdx.x == 0) g_xavg[bc] = red[0] * (1.f / (float)NPIX);
}

// =====================================================================
// Kernel 2: per-(head,batch) SE gate, exact top-k threshold (bitonic
// sort of 256), deterministic compaction of active channels.
// grid = 64 blocks (hb = h*16 + b), 256 threads
// =====================================================================
__global__ void se_kernel(const float* __restrict__ fc1,   // [4][16][256]
                          const float* __restrict__ fc2,   // [4][256][16]
                          const float* __restrict__ fcb,   // [4][256]
                          const int*   inact_p)
{
    __shared__ float sav[256];
    __shared__ float sy[16];
    __shared__ float ssort[256];
    __shared__ int   wcnt[8];
    __shared__ int   woff[9];

    int hb = blockIdx.x;
    int h  = hb >> 4, b = hb & 15;
    int tid = threadIdx.x;

    sav[tid] = g_xavg[b*CIN + tid];
    __syncthreads();

    if (tid < 16) {
        const float* w = fc1 + (h*16 + tid)*256;
        float s = 0.f;
        #pragma unroll 8
        for (int c = 0; c < 256; ++c) s = fmaf(w[c], sav[c], s);
        sy[tid] = fmaxf(s, 0.f);
    }
    __syncthreads();

    float m;
    {
        const float* w = fc2 + ((size_t)(h*256 + tid)) * 16;
        float s = fcb[h*256 + tid];
        #pragma unroll
        for (int r = 0; r < 16; ++r) s = fmaf(w[r], sy[r], s);
        m = fmaxf(s, 0.f);
    }
    ssort[tid] = m;
    __syncthreads();

    // lasso partial (pre-threshold mask): reuse sav
    sav[tid] = m;
    __syncthreads();
    for (int st = 128; st > 0; st >>= 1) {
        if (tid < st) sav[tid] += sav[tid + st];
        __syncthreads();
    }
    if (tid == 0) g_lasso_part[hb] = sav[0];
    __syncthreads();

    // bitonic sort ascending
    for (int k = 2; k <= 256; k <<= 1) {
        for (int j = k >> 1; j > 0; j >>= 1) {
            int ixj = tid ^ j;
            if (ixj > tid) {
                float va = ssort[tid], vb = ssort[ixj];
                bool up = ((tid & k) == 0);
                if ((va > vb) == up) { ssort[tid] = vb; ssort[ixj] = va; }
            }
            __syncthreads();
        }
    }

    int inact = 192;
    if (inact_p) {
        int iv = *inact_p;
        if (iv < 0 || iv > 256) {
            float f = __int_as_float(iv);
            iv = (f >= 0.f && f <= 256.f) ? (int)(f + 0.5f) : 192;
        }
        inact = iv;
    }
    float thresh = (inact > 0) ? ssort[min(inact,256) - 1] : -1e30f;

    bool keep = (m > thresh);
    unsigned ball = __ballot_sync(0xffffffffu, keep);
    int wid = tid >> 5, lane = tid & 31;
    if (lane == 0) wcnt[wid] = __popc(ball);
    __syncthreads();
    if (tid == 0) {
        int o = 0;
        #pragma unroll
        for (int w = 0; w < 8; ++w) { woff[w] = o; o += wcnt[w]; }
        woff[8] = o;
        g_act_cnt[hb] = o;
    }
    __syncthreads();
    // zero-pad to full chunk boundary for safe reads
    int total = woff[8];
    int padded = (total + 15) & ~15;
    if (tid >= total && tid < padded) {
        g_act_idx[hb*256 + tid] = 0;
        g_act_val[hb*256 + tid] = 0.f;
    }
    if (keep) {
        int slot = woff[wid] + __popc(ball & ((1u << lane) - 1));
        g_act_idx[hb*256 + slot] = tid;
        g_act_val[hb*256 + slot] = m;
    }
}

// =====================================================================
// Kernel 2b: final lasso reduction -> out[NOUT]
// =====================================================================
__global__ void lasso_kernel(float* __restrict__ out)
{
    __shared__ float red[64];
    int tid = threadIdx.x;
    red[tid] = g_lasso_part[tid];
    __syncthreads();
    for (int st = 32; st > 0; st >>= 1) {
        if (tid < st) red[tid] += red[tid + st];
        __syncthreads();
    }
    if (tid == 0) out[NOUT] = red[0] * (1.f / (float)(BATCH*CIN));
}

// =====================================================================
// Kernel 3: sparse grouped conv. Per (head,batch): gather <=64 active
// channels, apply BN+ReLU+mask on the fly, direct 3x3 conv to 64 ocs.
// grid = (14 row-tiles, 64 hb), block = (28,8) = 224 threads.
// Thread tile: 8 out-channels x 8 pixels in registers.
// =====================================================================
#define XTILE (16*6*58)   // 5568 floats
#define WTILE (64*16*9)   // 9216 floats
#define SMEMF (XTILE + WTILE + 16*3 + 16)   // + channel consts (a,b,m) + idx

__global__ __launch_bounds__(224, 2)
void conv_kernel(const float* __restrict__ x,
                 const float* __restrict__ gmm,
                 const float* __restrict__ bet,
                 const float* __restrict__ mea,
                 const float* __restrict__ var,
                 const float* __restrict__ conv_w,   // [4][64][256][3][3]
                 float* __restrict__ out)
{
    extern __shared__ float smem[];
    float* sx  = smem;                 // [16][6][58]
    float* sw  = smem + XTILE;         // [64 oc][16 ic][9]
    float* sca = sw + WTILE;           // [16]
    float* scb = sca + 16;
    float* scm = scb + 16;
    int*   sch = (int*)(scm + 16);

    int hb = blockIdx.y;
    int h  = hb >> 4, b = hb & 15;
    int r0 = blockIdx.x * 4;

    int pg  = threadIdx.x;             // 0..27 pixel group
    int og  = threadIdx.y;             // 0..7  oc group
    int tid = og * 28 + pg;
    int prow = pg / 7;                 // row within tile (0..3)
    int pcol = (pg % 7) * 8;           // col base (0..48)

    int cnt = g_act_cnt[hb];
    int nchunks = (cnt + 15) >> 4;

    float acc[8][8];
    #pragma unroll
    for (int a = 0; a < 8; ++a)
        #pragma unroll
        for (int i = 0; i < 8; ++i) acc[a][i] = 0.f;

    for (int ck = 0; ck < nchunks; ++ck) {
        __syncthreads();
        if (tid < 16) {
            int pos = ck*16 + tid;
            int ch = 0; float mv = 0.f;
            if (pos < cnt) { ch = g_act_idx[hb*256 + pos]; mv = g_act_val[hb*256 + pos]; }
            float a  = gmm[ch] * rsqrtf(var[ch] + BN_EPS);
            sca[tid] = a;
            scb[tid] = bet[ch] - mea[ch] * a;
            scm[tid] = mv;
            sch[tid] = ch;
        }
        __syncthreads();

        // stage input slab: 16 ch x 6 rows x 58 cols (BN+ReLU+mask fused)
        for (int idx = tid; idx < XTILE; idx += 224) {
            int icc = idx / 348;
            int rem = idx - icc*348;
            int rr  = rem / 58;
            int cc  = rem - rr*58;
            int gr  = r0 - 1 + rr;
            int gc  = cc - 1;
            float v = 0.f;
            float mv = scm[icc];
            if ((unsigned)gr < (unsigned)HH && (unsigned)gc < (unsigned)WW && mv != 0.f) {
                float xv = x[(((size_t)b*CIN + sch[icc])*HH + gr)*WW + gc];
                v = fmaxf(fmaf(xv, sca[icc], scb[icc]), 0.f) * mv;
            }
            sx[idx] = v;
        }
        // stage gathered weights: [oc][ic][9]
        for (int idx = tid; idx < WTILE; idx += 224) {
            int oc  = idx / 144;
            int rem = idx - oc*144;
            int icc = rem / 9;
            int tap = rem - icc*9;
            sw[idx] = conv_w[(((size_t)(h*CPER + oc))*CIN + sch[icc])*9 + tap];
        }
        __syncthreads();

        // compute: 16 ic x 9 taps x (8 oc x 8 px) FMAs
        for (int icc = 0; icc < 16; ++icc) {
            const float* xs = sx + icc*348 + prow*58 + pcol;
            const float* wp = sw + og*8*144 + icc*9;
            #pragma unroll
            for (int ky = 0; ky < 3; ++ky) {
                #pragma unroll
                for (int kx = 0; kx < 3; ++kx) {
                    float wv[8];
                    #pragma unroll
                    for (int a = 0; a < 8; ++a) wv[a] = wp[a*144 + ky*3 + kx];
                    float xv[8];
                    #pragma unroll
                    for (int i = 0; i < 8; ++i) xv[i] = xs[ky*58 + kx + i];
                    #pragma unroll
                    for (int a = 0; a < 8; ++a)
                        #pragma unroll
                        for (int i = 0; i < 8; ++i)
                            acc[a][i] = fmaf(wv[a], xv[i], acc[a][i]);
                }
            }
        }
    }

    // store: out channel = oc*HEADS + h  (the transpose in the reference)
    #pragma unroll
    for (int a = 0; a < 8; ++a) {
        int oc = og*8 + a;
        int co = oc*HEADS + h;
        size_t base = (((size_t)b*(HEADS*CPER) + co)*HH + (r0 + prow))*WW + pcol;
        float4 v0 = make_float4(acc[a][0], acc[a][1], acc[a][2], acc[a][3]);
        float4 v1 = make_float4(acc[a][4], acc[a][5], acc[a][6], acc[a][7]);
        *reinterpret_cast<float4*>(out + base)     = v0;
        *reinterpret_cast<float4*>(out + base + 4) = v1;
    }
}

// =====================================================================
// host launcher
// =====================================================================
extern "C" void kernel_launch(void* const* d_in, const int* in_sizes, int n_in,
                              void* d_out, int out_size)
{
    const float* x    = (const float*)d_in[0];
    const float* gmm  = (const float*)d_in[1];
    const float* bet  = (const float*)d_in[2];
    const float* mea  = (const float*)d_in[3];
    const float* var  = (const float*)d_in[4];
    const float* fc1  = (const float*)d_in[5];
    const float* fc2  = (const float*)d_in[6];
    const float* fcb  = (const float*)d_in[7];
    const float* cw   = (const float*)d_in[8];
    const int*   inact = (n_in > 9) ? (const int*)d_in[9] : nullptr;
    float* out = (float*)d_out;

    bn_pool_kernel<<<BATCH*CIN, 256>>>(x, gmm, bet, mea, var);
    se_kernel<<<HB_N, 256>>>(fc1, fc2, fcb, inact);
    if (out_size > NOUT) lasso_kernel<<<1, 64>>>(out);

    size_t smem_bytes = SMEMF * sizeof(float);
    cudaFuncSetAttribute(conv_kernel, cudaFuncAttributeMaxDynamicSharedMemorySize,
                         (int)smem_bytes);
    dim3 grid(HH/4, HB_N);
    dim3 blk(28, 8);
    conv_kernel<<<grid, blk, smem_bytes>>>(x, gmm, bet, mea, var, cw, out);
}

// round 2
// speedup vs baseline: 1.1398x; 1.1398x over previous
#include <cuda_runtime.h>
#include <cuda_bf16.h>
#include <math.h>

#define BATCH   16
#define CIN     256
#define HH      56
#define WW      56
#define HEADS   4
#define CPER    64          // C_OUT / HEADS
#define HB_N    (HEADS*BATCH)   // 64
#define NPIX    (HH*WW)         // 3136
#define NOUT    (BATCH*HEADS*CPER*NPIX)  // 12,845,056
#define BN_EPS  1e-5f

// ---------------- device scratch (no allocations allowed) ----------------
__device__ float g_xavg[BATCH*CIN];
__device__ int   g_act_idx[HB_N*256];
__device__ float g_act_val[HB_N*256];
__device__ int   g_act_cnt[HB_N];
__device__ float g_lasso_part[HB_N];

// =====================================================================
// Kernel 1: BN(inference)+ReLU fused global average pool
// =====================================================================
__global__ void bn_pool_kernel(const float* __restrict__ x,
                               const float* __restrict__ gmm,
                               const float* __restrict__ bet,
                               const float* __restrict__ mea,
                               const float* __restrict__ var)
{
    int bc = blockIdx.x;            // b*CIN + c
    int c  = bc & (CIN-1);
    float a  = gmm[c] * rsqrtf(var[c] + BN_EPS);
    float sh = bet[c] - mea[c] * a;
    const float* xp = x + (size_t)bc * NPIX;
    float s = 0.f;
    for (int i = threadIdx.x; i < NPIX; i += 256)
        s += fmaxf(fmaf(xp[i], a, sh), 0.f);
    __shared__ float red[256];
    red[threadIdx.x] = s;
    __syncthreads();
    for (int st = 128; st > 0; st >>= 1) {
        if (threadIdx.x < st) red[threadIdx.x] += red[threadIdx.x + st];
        __syncthreads();
    }
    if (threadIdx.x == 0) g_xavg[bc] = red[0] * (1.f / (float)NPIX);
}

// =====================================================================
// Kernel 2: SE gate + exact top-k threshold + compaction
// =====================================================================
__global__ void se_kernel(const float* __restrict__ fc1,   // [4][16][256]
                          const float* __restrict__ fc2,   // [4][256][16]
                          const float* __restrict__ fcb,   // [4][256]
                          const int*   inact_p)
{
    __shared__ float sav[256];
    __shared__ float sy[16];
    __shared__ float ssort[256];
    __shared__ int   wcnt[8];
    __shared__ int   woff[9];

    int hb = blockIdx.x;
    int h  = hb >> 4, b = hb & 15;
    int tid = threadIdx.x;

    sav[tid] = g_xavg[b*CIN + tid];
    __syncthreads();

    if (tid < 16) {
        const float* w = fc1 + (h*16 + tid)*256;
        float s = 0.f;
        #pragma unroll 8
        for (int c = 0; c < 256; ++c) s = fmaf(w[c], sav[c], s);
        sy[tid] = fmaxf(s, 0.f);
    }
    __syncthreads();

    float m;
    {
        const float* w = fc2 + ((size_t)(h*256 + tid)) * 16;
        float s = fcb[h*256 + tid];
        #pragma unroll
        for (int r = 0; r < 16; ++r) s = fmaf(w[r], sy[r], s);
        m = fmaxf(s, 0.f);
    }
    ssort[tid] = m;
    __syncthreads();

    sav[tid] = m;
    __syncthreads();
    for (int st = 128; st > 0; st >>= 1) {
        if (tid < st) sav[tid] += sav[tid + st];
        __syncthreads();
    }
    if (tid == 0) g_lasso_part[hb] = sav[0];
    __syncthreads();

    // bitonic sort ascending
    for (int k = 2; k <= 256; k <<= 1) {
        for (int j = k >> 1; j > 0; j >>= 1) {
            int ixj = tid ^ j;
            if (ixj > tid) {
                float va = ssort[tid], vb = ssort[ixj];
                bool up = ((tid & k) == 0);
                if ((va > vb) == up) { ssort[tid] = vb; ssort[ixj] = va; }
            }
            __syncthreads();
        }
    }

    int inact = 192;
    if (inact_p) {
        int iv = *inact_p;
        if (iv < 0 || iv > 256) {
            float f = __int_as_float(iv);
            iv = (f >= 0.f && f <= 256.f) ? (int)(f + 0.5f) : 192;
        }
        inact = iv;
    }
    float thresh = (inact > 0) ? ssort[min(inact,256) - 1] : -1e30f;

    bool keep = (m > thresh);
    unsigned ball = __ballot_sync(0xffffffffu, keep);
    int wid = tid >> 5, lane = tid & 31;
    if (lane == 0) wcnt[wid] = __popc(ball);
    __syncthreads();
    if (tid == 0) {
        int o = 0;
        #pragma unroll
        for (int w = 0; w < 8; ++w) { woff[w] = o; o += wcnt[w]; }
        woff[8] = o;
        g_act_cnt[hb] = o;
    }
    __syncthreads();
    int total = woff[8];
    int padded = (total + 15) & ~15;
    if (tid >= total && tid < padded) {
        g_act_idx[hb*256 + tid] = 0;
        g_act_val[hb*256 + tid] = 0.f;
    }
    if (keep) {
        int slot = woff[wid] + __popc(ball & ((1u << lane) - 1));
        g_act_idx[hb*256 + slot] = tid;
        g_act_val[hb*256 + slot] = m;
    }
}

// =====================================================================
// Kernel 2b: final lasso reduction -> out[NOUT]
// =====================================================================
__global__ void lasso_kernel(float* __restrict__ out)
{
    __shared__ float red[64];
    int tid = threadIdx.x;
    red[tid] = g_lasso_part[tid];
    __syncthreads();
    for (int st = 32; st > 0; st >>= 1) {
        if (tid < st) red[tid] += red[tid + st];
        __syncthreads();
    }
    if (tid == 0) out[NOUT] = red[0] * (1.f / (float)(BATCH*CIN));
}

// =====================================================================
// Kernel 3: sparse grouped conv, f32x2 packed FMA version.
//   - weights staged as [ic16][tap9][oc64] -> oc-pair LDS.64
//   - x slab pitch 60 (16B aligned), vector loads + dup-packed pairs
//   - acc pairs along oc: 4 pairs x 8 px of 64-bit f32x2
// grid = (14 row-tiles, 64 hb), block = (28,8) = 224 threads.
// =====================================================================
#define XPITCH 60
#define XTILE (16*6*XPITCH)   // 5760 floats
#define WTILE (16*9*64)       // 9216 floats
#define SMEMF (XTILE + WTILE + 16*3 + 16)

typedef unsigned long long ull;

__device__ __forceinline__ ull fma2(ull a, ull b, ull c) {
    ull d;
    asm("fma.rn.f32x2 %0, %1, %2, %3;" : "=l"(d) : "l"(a), "l"(b), "l"(c));
    return d;
}
__device__ __forceinline__ ull dup2(float v) {
    ull d;
    asm("mov.b64 %0, {%1, %1};" : "=l"(d) : "f"(v));
    return d;
}

__global__ __launch_bounds__(224, 2)
void conv_kernel(const float* __restrict__ x,
                 const float* __restrict__ gmm,
                 const float* __restrict__ bet,
                 const float* __restrict__ mea,
                 const float* __restrict__ var,
                 const float* __restrict__ conv_w,   // [4][64][256][3][3]
                 float* __restrict__ out)
{
    extern __shared__ float smem[];
    float* sx  = smem;                 // [16][6][60]
    float* sw  = smem + XTILE;         // [16 ic][9 tap][64 oc]
    float* sca = sw + WTILE;           // [16]
    float* scb = sca + 16;
    float* scm = scb + 16;
    int*   sch = (int*)(scm + 16);

    int hb = blockIdx.y;
    int h  = hb >> 4, b = hb & 15;
    int r0 = blockIdx.x * 4;

    int pg  = threadIdx.x;             // 0..27
    int og  = threadIdx.y;             // 0..7
    int tid = og * 28 + pg;
    int prow = pg / 7;                 // 0..3
    int pcol = (pg % 7) * 8;           // 0..48

    int cnt = g_act_cnt[hb];
    int nchunks = (cnt + 15) >> 4;

    ull acc2[4][8];
    #pragma unroll
    for (int a = 0; a < 4; ++a)
        #pragma unroll
        for (int i = 0; i < 8; ++i) acc2[a][i] = 0ull;

    for (int ck = 0; ck < nchunks; ++ck) {
        __syncthreads();
        if (tid < 16) {
            int pos = ck*16 + tid;
            int ch = 0; float mv = 0.f;
            if (pos < cnt) { ch = g_act_idx[hb*256 + pos]; mv = g_act_val[hb*256 + pos]; }
            float a  = gmm[ch] * rsqrtf(var[ch] + BN_EPS);
            sca[tid] = a;
            scb[tid] = bet[ch] - mea[ch] * a;
            scm[tid] = mv;
            sch[tid] = ch;
        }
        __syncthreads();

        // stage input slab: 16 ch x 6 rows x 60 cols (BN+ReLU+mask fused)
        for (int idx = tid; idx < XTILE; idx += 224) {
            int icc = idx / (6*XPITCH);
            int rem = idx - icc*(6*XPITCH);
            int rr  = rem / XPITCH;
            int cc  = rem - rr*XPITCH;
            int gr  = r0 - 1 + rr;
            int gc  = cc - 1;
            float v = 0.f;
            float mv = scm[icc];
            if ((unsigned)gr < (unsigned)HH && (unsigned)gc < (unsigned)WW && mv != 0.f) {
                float xv = x[(((size_t)b*CIN + sch[icc])*HH + gr)*WW + gc];
                v = fmaxf(fmaf(xv, sca[icc], scb[icc]), 0.f) * mv;
            }
            sx[idx] = v;
        }
        // stage weights as [ic][tap][oc]
        for (int idx = tid; idx < WTILE; idx += 224) {
            int oc  = idx & 63;
            int t2  = idx >> 6;
            int tap = t2 % 9;
            int icc = t2 / 9;
            sw[idx] = conv_w[(((size_t)(h*CPER + oc))*CIN + sch[icc])*9 + tap];
        }
        __syncthreads();

        // compute
        #pragma unroll 1
        for (int icc = 0; icc < 16; ++icc) {
            const float* xrb = sx + icc*(6*XPITCH) + prow*XPITCH + pcol;
            const float* wb  = sw + icc*9*64 + og*8;
            #pragma unroll
            for (int ky = 0; ky < 3; ++ky) {
                const float* xr = xrb + ky*XPITCH;
                float4 A  = *reinterpret_cast<const float4*>(xr);
                float4 Bv = *reinterpret_cast<const float4*>(xr + 4);
                float2 Cv = *reinterpret_cast<const float2*>(xr + 8);
                ull xd[10];
                xd[0] = dup2(A.x); xd[1] = dup2(A.y); xd[2] = dup2(A.z); xd[3] = dup2(A.w);
                xd[4] = dup2(Bv.x); xd[5] = dup2(Bv.y); xd[6] = dup2(Bv.z); xd[7] = dup2(Bv.w);
                xd[8] = dup2(Cv.x); xd[9] = dup2(Cv.y);
                #pragma unroll
                for (int kx = 0; kx < 3; ++kx) {
                    const float* wp = wb + (ky*3 + kx)*64;
                    ull w0 = *reinterpret_cast<const ull*>(wp + 0);
                    ull w1 = *reinterpret_cast<const ull*>(wp + 2);
                    ull w2 = *reinterpret_cast<const ull*>(wp + 4);
                    ull w3 = *reinterpret_cast<const ull*>(wp + 6);
                    #pragma unroll
                    for (int i = 0; i < 8; ++i) {
                        ull xv = xd[kx + i];
                        acc2[0][i] = fma2(w0, xv, acc2[0][i]);
                        acc2[1][i] = fma2(w1, xv, acc2[1][i]);
                        acc2[2][i] = fma2(w2, xv, acc2[2][i]);
                        acc2[3][i] = fma2(w3, xv, acc2[3][i]);
                    }
                }
            }
        }
    }

    // store: out channel = oc*HEADS + h
    #pragma unroll
    for (int a = 0; a < 4; ++a) {
        float lo[8], hi[8];
        #pragma unroll
        for (int i = 0; i < 8; ++i) {
            unsigned l32, h32;
            asm("mov.b64 {%0, %1}, %2;" : "=r"(l32), "=r"(h32) : "l"(acc2[a][i]));
            lo[i] = __uint_as_float(l32);
            hi[i] = __uint_as_float(h32);
        }
        int oc0 = og*8 + 2*a;
        size_t base0 = (((size_t)b*(HEADS*CPER) + (oc0*HEADS + h))*HH + (r0 + prow))*WW + pcol;
        size_t base1 = (((size_t)b*(HEADS*CPER) + ((oc0+1)*HEADS + h))*HH + (r0 + prow))*WW + pcol;
        *reinterpret_cast<float4*>(out + base0)     = make_float4(lo[0], lo[1], lo[2], lo[3]);
        *reinterpret_cast<float4*>(out + base0 + 4) = make_float4(lo[4], lo[5], lo[6], lo[7]);
        *reinterpret_cast<float4*>(out + base1)     = make_float4(hi[0], hi[1], hi[2], hi[3]);
        *reinterpret_cast<float4*>(out + base1 + 4) = make_float4(hi[4], hi[5], hi[6], hi[7]);
    }
}

// =====================================================================
// host launcher
// =====================================================================
extern "C" void kernel_launch(void* const* d_in, const int* in_sizes, int n_in,
                              void* d_out, int out_size)
{
    const float* x    = (const float*)d_in[0];
    const float* gmm  = (const float*)d_in[1];
    const float* bet  = (const float*)d_in[2];
    const float* mea  = (const float*)d_in[3];
    const float* var  = (const float*)d_in[4];
    const float* fc1  = (const float*)d_in[5];
    const float* fc2  = (const float*)d_in[6];
    const float* fcb  = (const float*)d_in[7];
    const float* cw   = (const float*)d_in[8];
    const int*   inact = (n_in > 9) ? (const int*)d_in[9] : nullptr;
    float* out = (float*)d_out;

    bn_pool_kernel<<<BATCH*CIN, 256>>>(x, gmm, bet, mea, var);
    se_kernel<<<HB_N, 256>>>(fc1, fc2, fcb, inact);
    if (out_size > NOUT) lasso_kernel<<<1, 64>>>(out);

    size_t smem_bytes = SMEMF * sizeof(float);
    cudaFuncSetAttribute(conv_kernel, cudaFuncAttributeMaxDynamicSharedMemorySize,
                         (int)smem_bytes);
    dim3 grid(HH/4, HB_N);
    dim3 blk(28, 8);
    conv_kernel<<<grid, blk, smem_bytes>>>(x, gmm, bet, mea, var, cw, out);
}